// round 5
// baseline (speedup 1.0000x reference)
#include <cuda_runtime.h>
#include <cuda_bf16.h>

#define N_NODES 50000
#define N_EDGES 800000
#define FIN 128
#define HID 256

// ---------------- scratch (no allocation allowed) ----------------
__device__ float g_bufA[N_NODES * HID];   // xw1 / xw2
__device__ float g_bufB[N_NODES * HID];   // h1
__device__ float g_dinv[N_NODES];
__device__ float g_w[N_EDGES];            // per-edge norm = dinv[src]*dinv[dst]
__device__ int   g_cnt[N_NODES];
__device__ int   g_rowptr[N_NODES + 1];
__device__ int   g_cursor[N_NODES];
__device__ int   g_col[N_EDGES];
__device__ int   g_bsums[256];

// ---------------- CSR build ----------------
__global__ void zero_cnt_kernel() {
    int i = blockIdx.x * blockDim.x + threadIdx.x;
    if (i < N_NODES) g_cnt[i] = 0;
}

__global__ void count_kernel(const int* __restrict__ ei) {
    int e = blockIdx.x * blockDim.x + threadIdx.x;
    if (e < N_EDGES) {
        int dst = ei[N_EDGES + e];
        atomicAdd(&g_cnt[dst], 1);
    }
}

// exclusive scan of g_cnt into g_rowptr: per-block pass
__global__ void scan_blocks_kernel() {
    __shared__ int sh[256];
    int i = blockIdx.x * 256 + threadIdx.x;
    int v = (i < N_NODES) ? g_cnt[i] : 0;
    sh[threadIdx.x] = v;
    __syncthreads();
    #pragma unroll
    for (int off = 1; off < 256; off <<= 1) {
        int t = (threadIdx.x >= off) ? sh[threadIdx.x - off] : 0;
        __syncthreads();
        sh[threadIdx.x] += t;
        __syncthreads();
    }
    if (i < N_NODES) g_rowptr[i] = sh[threadIdx.x] - v;  // exclusive within block
    if (threadIdx.x == 255) g_bsums[blockIdx.x] = sh[255];
}

__global__ void scan_bsums_kernel(int nb) {
    __shared__ int sh[256];
    int v = (threadIdx.x < nb) ? g_bsums[threadIdx.x] : 0;
    sh[threadIdx.x] = v;
    __syncthreads();
    #pragma unroll
    for (int off = 1; off < 256; off <<= 1) {
        int t = (threadIdx.x >= off) ? sh[threadIdx.x - off] : 0;
        __syncthreads();
        sh[threadIdx.x] += t;
        __syncthreads();
    }
    if (threadIdx.x < nb) g_bsums[threadIdx.x] = sh[threadIdx.x] - v;  // exclusive
}

__global__ void scan_add_kernel() {
    int i = blockIdx.x * 256 + threadIdx.x;
    if (i < N_NODES) {
        int v = g_rowptr[i] + g_bsums[blockIdx.x];
        g_rowptr[i] = v;
        g_cursor[i] = v;
    }
    if (i == 0) g_rowptr[N_NODES] = N_EDGES;
}

__global__ void dinv_kernel() {
    int i = blockIdx.x * blockDim.x + threadIdx.x;
    if (i < N_NODES) {
        float deg = (float)g_cnt[i] + 1.0f;  // + self loop; always >= 1
        g_dinv[i] = rsqrtf(deg);
    }
}

__global__ void fill_kernel(const int* __restrict__ ei) {
    int e = blockIdx.x * blockDim.x + threadIdx.x;
    if (e < N_EDGES) {
        int src = ei[e];
        int dst = ei[N_EDGES + e];
        int pos = atomicAdd(&g_cursor[dst], 1);
        g_col[pos] = src;
        g_w[pos] = g_dinv[src] * g_dinv[dst];
    }
}

// ---------------- SIMT fp32 GEMM: C[M,N] = A[M,K] @ B[K,N] ----------------
// ASEL: 0 -> A = external pointer (x), 1 -> A = g_bufB. C is always g_bufA.
// BM=128, BN=128, BK=16, 256 threads, 8x8 per thread
template <int ASEL>
__global__ __launch_bounds__(256) void gemm_kernel(
    const float* __restrict__ Aext, const float* __restrict__ B,
    int M, int K, int N)
{
    const float* __restrict__ A = (ASEL == 0) ? Aext : (const float*)g_bufB;
    float* __restrict__ C = g_bufA;

    const int BM = 128, BN = 128, BK = 16, TM = 8, TN = 8;
    __shared__ float As[BK][BM];  // transposed: As[k][m]
    __shared__ float Bs[BK][BN];

    const int tid = threadIdx.x;
    const int bm = blockIdx.y * BM;
    const int bn = blockIdx.x * BN;
    const int tcol = tid % (BN / TN);  // 0..15
    const int trow = tid / (BN / TN);  // 0..15

    float acc[TM][TN];
    #pragma unroll
    for (int i = 0; i < TM; i++)
        #pragma unroll
        for (int j = 0; j < TN; j++) acc[i][j] = 0.f;

    for (int k0 = 0; k0 < K; k0 += BK) {
        #pragma unroll
        for (int i = tid; i < BM * BK; i += 256) {
            int r = i / BK, c = i % BK;
            int gr = bm + r;
            float v = 0.f;
            if (gr < M) v = A[(long)gr * K + k0 + c];
            As[c][r] = v;
        }
        #pragma unroll
        for (int i = tid; i < BK * BN; i += 256) {
            int r = i / BN, c = i % BN;
            Bs[r][c] = B[(long)(k0 + r) * N + bn + c];
        }
        __syncthreads();
        #pragma unroll
        for (int kk = 0; kk < BK; kk++) {
            float ra[TM], rb[TN];
            #pragma unroll
            for (int i = 0; i < TM; i++) ra[i] = As[kk][trow * TM + i];
            #pragma unroll
            for (int j = 0; j < TN; j++) rb[j] = Bs[kk][tcol * TN + j];
            #pragma unroll
            for (int i = 0; i < TM; i++)
                #pragma unroll
                for (int j = 0; j < TN; j++)
                    acc[i][j] += ra[i] * rb[j];
        }
        __syncthreads();
    }
    #pragma unroll
    for (int i = 0; i < TM; i++) {
        int gr = bm + trow * TM + i;
        if (gr < M) {
            #pragma unroll
            for (int j = 0; j < TN; j++)
                C[(long)gr * N + bn + tcol * TN + j] = acc[i][j];
        }
    }
}

// ---------------- aggregation: one warp per node, 8 contiguous feats/thread --
// in = g_bufA. out[node,:] = relu( sum_in w*in[src,:] + dinv^2*in[node,:] + bias )
// FUSE_FC=false: write to g_bufB.  FUSE_FC=true: dot with Wfc -> scalar outp[node].
template <bool FUSE_FC>
__global__ __launch_bounds__(256) void agg_kernel(
    const float* __restrict__ bias,
    float* __restrict__ outp,
    const float* __restrict__ wfc, const float* __restrict__ bfc)
{
    const float* __restrict__ in = (const float*)g_bufA;

    int warp = (blockIdx.x * blockDim.x + threadIdx.x) >> 5;
    int lane = threadIdx.x & 31;
    if (warp >= N_NODES) return;
    const int node = warp;
    const int start = g_rowptr[node];
    const int end   = g_rowptr[node + 1];
    const float di = g_dinv[node];
    const float selfw = di * di;

    const int fo = lane * 2;  // float4 index within 64-float4 row

    float4 a0, a1;
    {
        const float4* row = (const float4*)(in + (long)node * HID);
        float4 v0 = row[fo], v1 = row[fo + 1];
        a0.x = selfw * v0.x; a0.y = selfw * v0.y; a0.z = selfw * v0.z; a0.w = selfw * v0.w;
        a1.x = selfw * v1.x; a1.y = selfw * v1.y; a1.z = selfw * v1.z; a1.w = selfw * v1.w;
    }

    for (int e0 = start; e0 < end; e0 += 32) {
        int e = e0 + lane;
        int src = 0; float w = 0.f;
        if (e < end) { src = g_col[e]; w = g_w[e]; }
        int cnt = min(32, end - e0);
        for (int j = 0; j < cnt; j++) {
            int   s  = __shfl_sync(0xffffffff, src, j);
            float ww = __shfl_sync(0xffffffff, w, j);
            const float4* row = (const float4*)(in + (long)s * HID);
            float4 v0 = row[fo], v1 = row[fo + 1];
            a0.x += ww * v0.x; a0.y += ww * v0.y; a0.z += ww * v0.z; a0.w += ww * v0.w;
            a1.x += ww * v1.x; a1.y += ww * v1.y; a1.z += ww * v1.z; a1.w += ww * v1.w;
        }
    }

    {
        const float4* b4 = (const float4*)bias;
        float4 b0 = b4[fo], b1v = b4[fo + 1];
        a0.x = fmaxf(a0.x + b0.x, 0.f);  a0.y = fmaxf(a0.y + b0.y, 0.f);
        a0.z = fmaxf(a0.z + b0.z, 0.f);  a0.w = fmaxf(a0.w + b0.w, 0.f);
        a1.x = fmaxf(a1.x + b1v.x, 0.f); a1.y = fmaxf(a1.y + b1v.y, 0.f);
        a1.z = fmaxf(a1.z + b1v.z, 0.f); a1.w = fmaxf(a1.w + b1v.w, 0.f);
    }

    if (!FUSE_FC) {
        float4* orow = (float4*)(g_bufB + (long)node * HID);
        orow[fo] = a0;
        orow[fo + 1] = a1;
    } else {
        const float4* w4 = (const float4*)wfc;
        float4 w0 = w4[fo], w1 = w4[fo + 1];
        float s = a0.x * w0.x + a0.y * w0.y + a0.z * w0.z + a0.w * w0.w
                + a1.x * w1.x + a1.y * w1.y + a1.z * w1.z + a1.w * w1.w;
        #pragma unroll
        for (int off = 16; off > 0; off >>= 1)
            s += __shfl_xor_sync(0xffffffff, s, off);
        if (lane == 0) outp[node] = s + bfc[0];
    }
}

// ---------------- launch ----------------
extern "C" void kernel_launch(void* const* d_in, const int* in_sizes, int n_in,
                              void* d_out, int out_size)
{
    const float* x   = (const float*)d_in[0];
    const int*   ei  = (const int*)d_in[1];    // int32: JAX x64-disabled demotes int64
    const float* W1  = (const float*)d_in[2];
    const float* b1  = (const float*)d_in[3];
    const float* W2  = (const float*)d_in[4];
    const float* b2  = (const float*)d_in[5];
    const float* Wfc = (const float*)d_in[6];
    const float* bfc = (const float*)d_in[7];
    float* out = (float*)d_out;

    const int NB_N = (N_NODES + 255) / 256;   // 196
    const int NB_E = (N_EDGES + 255) / 256;   // 3125

    // CSR build + degree norms (recomputed every call; deterministic output)
    zero_cnt_kernel<<<NB_N, 256>>>();
    count_kernel<<<NB_E, 256>>>(ei);
    scan_blocks_kernel<<<NB_N, 256>>>();
    scan_bsums_kernel<<<1, 256>>>(NB_N);
    scan_add_kernel<<<NB_N, 256>>>();
    dinv_kernel<<<NB_N, 256>>>();
    fill_kernel<<<NB_E, 256>>>(ei);

    // layer 1: g_bufA = x @ W1 ; g_bufB = relu(agg(g_bufA) + b1)
    {
        dim3 grid(HID / 128, (N_NODES + 127) / 128);
        gemm_kernel<0><<<grid, 256>>>(x, W1, N_NODES, FIN, HID);
    }
    agg_kernel<false><<<(N_NODES * 32 + 255) / 256, 256>>>(b1, nullptr, nullptr, nullptr);

    // layer 2: g_bufA = g_bufB @ W2 ; out = relu(agg(g_bufA) + b2) @ Wfc + bfc
    {
        dim3 grid(HID / 128, (N_NODES + 127) / 128);
        gemm_kernel<1><<<grid, 256>>>(nullptr, W2, N_NODES, HID, HID);
    }
    agg_kernel<true><<<(N_NODES * 32 + 255) / 256, 256>>>(b2, out, Wfc, bfc);
}

// round 7
// speedup vs baseline: 3.1084x; 3.1084x over previous
#include <cuda_runtime.h>
#include <cuda_bf16.h>
#include <cstdint>

#define N_NODES 50000
#define N_EDGES 800000
#define FIN 128
#define HID 256

// ---------------- scratch (no allocation allowed) ----------------
__device__ float g_bufA[N_NODES * HID];   // xw1 / xw2
__device__ float g_bufB[N_NODES * HID];   // h1
__device__ float g_dinv[N_NODES];
__device__ float g_w[N_EDGES];            // per-edge norm = dinv[src]*dinv[dst]
__device__ int   g_cnt[N_NODES];
__device__ int   g_rowptr[N_NODES + 1];
__device__ int   g_cursor[N_NODES];
__device__ int   g_col[N_EDGES];
__device__ int   g_bsums[256];

// ---------------- CSR build ----------------
__global__ void zero_cnt_kernel() {
    int i = blockIdx.x * blockDim.x + threadIdx.x;
    if (i < N_NODES) g_cnt[i] = 0;
}

__global__ void count_kernel(const int* __restrict__ ei) {
    int e = blockIdx.x * blockDim.x + threadIdx.x;
    if (e < N_EDGES) {
        int dst = ei[N_EDGES + e];
        atomicAdd(&g_cnt[dst], 1);
    }
}

// exclusive scan of g_cnt into g_rowptr (per-block) + dinv fold
__global__ void scan_blocks_kernel() {
    __shared__ int sh[256];
    int i = blockIdx.x * 256 + threadIdx.x;
    int v = (i < N_NODES) ? g_cnt[i] : 0;
    if (i < N_NODES) g_dinv[i] = rsqrtf((float)v + 1.0f);  // self-loop included
    sh[threadIdx.x] = v;
    __syncthreads();
    #pragma unroll
    for (int off = 1; off < 256; off <<= 1) {
        int t = (threadIdx.x >= off) ? sh[threadIdx.x - off] : 0;
        __syncthreads();
        sh[threadIdx.x] += t;
        __syncthreads();
    }
    if (i < N_NODES) g_rowptr[i] = sh[threadIdx.x] - v;
    if (threadIdx.x == 255) g_bsums[blockIdx.x] = sh[255];
}

__global__ void scan_bsums_kernel(int nb) {
    __shared__ int sh[256];
    int v = (threadIdx.x < nb) ? g_bsums[threadIdx.x] : 0;
    sh[threadIdx.x] = v;
    __syncthreads();
    #pragma unroll
    for (int off = 1; off < 256; off <<= 1) {
        int t = (threadIdx.x >= off) ? sh[threadIdx.x - off] : 0;
        __syncthreads();
        sh[threadIdx.x] += t;
        __syncthreads();
    }
    if (threadIdx.x < nb) g_bsums[threadIdx.x] = sh[threadIdx.x] - v;
}

__global__ void scan_add_kernel() {
    int i = blockIdx.x * 256 + threadIdx.x;
    if (i < N_NODES) {
        int v = g_rowptr[i] + g_bsums[blockIdx.x];
        g_rowptr[i] = v;
        g_cursor[i] = v;
    }
    if (i == 0) g_rowptr[N_NODES] = N_EDGES;
}

__global__ void fill_kernel(const int* __restrict__ ei) {
    int e = blockIdx.x * blockDim.x + threadIdx.x;
    if (e < N_EDGES) {
        int src = ei[e];
        int dst = ei[N_EDGES + e];
        int pos = atomicAdd(&g_cursor[dst], 1);
        g_col[pos] = src;
        g_w[pos] = g_dinv[src] * g_dinv[dst];
    }
}

// ---------------- tf32 tensor-core GEMM: C[M,256] = A[M,K] @ B[K,256] -------
// BM=128, BN=64, BK=16. 256 threads = 8 warps in 4(m) x 2(n).
// Each warp computes 32x32 via m16n8k8 tf32 mma (2 m-tiles x 4 n-tiles).
// ASEL: 0 -> A = Aext (x), 1 -> A = g_bufB. C is always g_bufA.
__device__ __forceinline__ uint32_t f2tf32(float f) {
    uint32_t r;
    asm("cvt.rna.tf32.f32 %0, %1;" : "=r"(r) : "f"(f));
    return r;
}

template <int ASEL>
__global__ __launch_bounds__(256) void gemm_tf32_kernel(
    const float* __restrict__ Aext, const float* __restrict__ B, int M, int K)
{
    const float* __restrict__ A = (ASEL == 0) ? Aext : (const float*)g_bufB;
    float* __restrict__ C = g_bufA;

    __shared__ uint32_t As[128][20];  // [m][k], pad 16->20
    __shared__ uint32_t Bs[16][72];   // [k][n], pad 64->72

    const int tid = threadIdx.x;
    const int warp = tid >> 5, lane = tid & 31;
    const int warp_m = warp & 3, warp_n = warp >> 2;   // 4 x 2
    const int wm = warp_m * 32, wn = warp_n * 32;
    const int groupID = lane >> 2, tig = lane & 3;

    const int bm = blockIdx.y * 128;
    const int bn = blockIdx.x * 64;

    float acc[2][4][4];
    #pragma unroll
    for (int mt = 0; mt < 2; mt++)
        #pragma unroll
        for (int nt = 0; nt < 4; nt++)
            #pragma unroll
            for (int r = 0; r < 4; r++) acc[mt][nt][r] = 0.f;

    // staging indices
    const int ar = tid >> 2;          // 0..63
    const int ac = (tid & 3) * 4;     // 0,4,8,12
    const int br = tid >> 4;          // 0..15
    const int bc = (tid & 15) * 4;    // 0..60

    for (int k0 = 0; k0 < K; k0 += 16) {
        // stage A: 2 float4 per thread
        #pragma unroll
        for (int h = 0; h < 2; h++) {
            int r = ar + h * 64;
            int gr = bm + r;
            float4 v = make_float4(0.f, 0.f, 0.f, 0.f);
            if (gr < M) v = *(const float4*)(A + (long)gr * K + k0 + ac);
            As[r][ac + 0] = f2tf32(v.x);
            As[r][ac + 1] = f2tf32(v.y);
            As[r][ac + 2] = f2tf32(v.z);
            As[r][ac + 3] = f2tf32(v.w);
        }
        // stage B: 1 float4 per thread
        {
            float4 v = *(const float4*)(B + (long)(k0 + br) * HID + bn + bc);
            Bs[br][bc + 0] = f2tf32(v.x);
            Bs[br][bc + 1] = f2tf32(v.y);
            Bs[br][bc + 2] = f2tf32(v.z);
            Bs[br][bc + 3] = f2tf32(v.w);
        }
        __syncthreads();

        #pragma unroll
        for (int ks = 0; ks < 16; ks += 8) {
            uint32_t a[2][4];
            #pragma unroll
            for (int mt = 0; mt < 2; mt++) {
                int r = wm + mt * 16;
                a[mt][0] = As[r + groupID][ks + tig];
                a[mt][1] = As[r + groupID + 8][ks + tig];
                a[mt][2] = As[r + groupID][ks + tig + 4];
                a[mt][3] = As[r + groupID + 8][ks + tig + 4];
            }
            uint32_t b[4][2];
            #pragma unroll
            for (int nt = 0; nt < 4; nt++) {
                int c = wn + nt * 8 + groupID;
                b[nt][0] = Bs[ks + tig][c];
                b[nt][1] = Bs[ks + tig + 4][c];
            }
            #pragma unroll
            for (int mt = 0; mt < 2; mt++)
                #pragma unroll
                for (int nt = 0; nt < 4; nt++) {
                    asm volatile(
                        "mma.sync.aligned.m16n8k8.row.col.f32.tf32.tf32.f32 "
                        "{%0,%1,%2,%3}, {%4,%5,%6,%7}, {%8,%9}, {%0,%1,%2,%3};"
                        : "+f"(acc[mt][nt][0]), "+f"(acc[mt][nt][1]),
                          "+f"(acc[mt][nt][2]), "+f"(acc[mt][nt][3])
                        : "r"(a[mt][0]), "r"(a[mt][1]), "r"(a[mt][2]), "r"(a[mt][3]),
                          "r"(b[nt][0]), "r"(b[nt][1]));
                }
        }
        __syncthreads();
    }

    // epilogue
    #pragma unroll
    for (int mt = 0; mt < 2; mt++) {
        #pragma unroll
        for (int nt = 0; nt < 4; nt++) {
            int r0 = bm + wm + mt * 16 + groupID;
            int c = bn + wn + nt * 8 + tig * 2;
            if (r0 < M) {
                float2 v = make_float2(acc[mt][nt][0], acc[mt][nt][1]);
                *(float2*)(C + (long)r0 * HID + c) = v;
            }
            if (r0 + 8 < M) {
                float2 v = make_float2(acc[mt][nt][2], acc[mt][nt][3]);
                *(float2*)(C + (long)(r0 + 8) * HID + c) = v;
            }
        }
    }
}

// ---------------- aggregation: one warp per node, 8 contiguous feats/thread --
// in = g_bufA. out[node,:] = relu( sum_in w*in[src,:] + dinv^2*in[node,:] + bias )
// FUSE_FC=false: write to g_bufB.  FUSE_FC=true: dot with Wfc -> scalar outp[node].
template <bool FUSE_FC>
__global__ __launch_bounds__(256) void agg_kernel(
    const float* __restrict__ bias,
    float* __restrict__ outp,
    const float* __restrict__ wfc, const float* __restrict__ bfc)
{
    const float* __restrict__ in = (const float*)g_bufA;

    int warp = (blockIdx.x * blockDim.x + threadIdx.x) >> 5;
    int lane = threadIdx.x & 31;
    if (warp >= N_NODES) return;
    const int node = warp;
    const int start = g_rowptr[node];
    const int end   = g_rowptr[node + 1];
    const float di = g_dinv[node];
    const float selfw = di * di;

    const int fo = lane * 2;  // float4 index within 64-float4 row

    float4 a0, a1;
    {
        const float4* row = (const float4*)(in + (long)node * HID);
        float4 v0 = row[fo], v1 = row[fo + 1];
        a0.x = selfw * v0.x; a0.y = selfw * v0.y; a0.z = selfw * v0.z; a0.w = selfw * v0.w;
        a1.x = selfw * v1.x; a1.y = selfw * v1.y; a1.z = selfw * v1.z; a1.w = selfw * v1.w;
    }

    for (int e0 = start; e0 < end; e0 += 32) {
        int e = e0 + lane;
        int src = 0; float w = 0.f;
        if (e < end) { src = g_col[e]; w = g_w[e]; }
        int cnt = min(32, end - e0);
        int j = 0;
        for (; j + 4 <= cnt; j += 4) {
            int   s0 = __shfl_sync(0xffffffff, src, j);
            int   s1 = __shfl_sync(0xffffffff, src, j + 1);
            int   s2 = __shfl_sync(0xffffffff, src, j + 2);
            int   s3 = __shfl_sync(0xffffffff, src, j + 3);
            float w0 = __shfl_sync(0xffffffff, w, j);
            float w1 = __shfl_sync(0xffffffff, w, j + 1);
            float w2 = __shfl_sync(0xffffffff, w, j + 2);
            float w3 = __shfl_sync(0xffffffff, w, j + 3);
            const float4* r0 = (const float4*)(in + (long)s0 * HID);
            const float4* r1 = (const float4*)(in + (long)s1 * HID);
            const float4* r2 = (const float4*)(in + (long)s2 * HID);
            const float4* r3 = (const float4*)(in + (long)s3 * HID);
            float4 p0 = r0[fo], q0 = r0[fo + 1];
            float4 p1 = r1[fo], q1 = r1[fo + 1];
            float4 p2 = r2[fo], q2 = r2[fo + 1];
            float4 p3 = r3[fo], q3 = r3[fo + 1];
            a0.x += w0 * p0.x; a0.y += w0 * p0.y; a0.z += w0 * p0.z; a0.w += w0 * p0.w;
            a1.x += w0 * q0.x; a1.y += w0 * q0.y; a1.z += w0 * q0.z; a1.w += w0 * q0.w;
            a0.x += w1 * p1.x; a0.y += w1 * p1.y; a0.z += w1 * p1.z; a0.w += w1 * p1.w;
            a1.x += w1 * q1.x; a1.y += w1 * q1.y; a1.z += w1 * q1.z; a1.w += w1 * q1.w;
            a0.x += w2 * p2.x; a0.y += w2 * p2.y; a0.z += w2 * p2.z; a0.w += w2 * p2.w;
            a1.x += w2 * q2.x; a1.y += w2 * q2.y; a1.z += w2 * q2.z; a1.w += w2 * q2.w;
            a0.x += w3 * p3.x; a0.y += w3 * p3.y; a0.z += w3 * p3.z; a0.w += w3 * p3.w;
            a1.x += w3 * q3.x; a1.y += w3 * q3.y; a1.z += w3 * q3.z; a1.w += w3 * q3.w;
        }
        for (; j < cnt; j++) {
            int   s  = __shfl_sync(0xffffffff, src, j);
            float ww = __shfl_sync(0xffffffff, w, j);
            const float4* row = (const float4*)(in + (long)s * HID);
            float4 v0 = row[fo], v1 = row[fo + 1];
            a0.x += ww * v0.x; a0.y += ww * v0.y; a0.z += ww * v0.z; a0.w += ww * v0.w;
            a1.x += ww * v1.x; a1.y += ww * v1.y; a1.z += ww * v1.z; a1.w += ww * v1.w;
        }
    }

    {
        const float4* b4 = (const float4*)bias;
        float4 b0 = b4[fo], b1v = b4[fo + 1];
        a0.x = fmaxf(a0.x + b0.x, 0.f);  a0.y = fmaxf(a0.y + b0.y, 0.f);
        a0.z = fmaxf(a0.z + b0.z, 0.f);  a0.w = fmaxf(a0.w + b0.w, 0.f);
        a1.x = fmaxf(a1.x + b1v.x, 0.f); a1.y = fmaxf(a1.y + b1v.y, 0.f);
        a1.z = fmaxf(a1.z + b1v.z, 0.f); a1.w = fmaxf(a1.w + b1v.w, 0.f);
    }

    if (!FUSE_FC) {
        float4* orow = (float4*)(g_bufB + (long)node * HID);
        orow[fo] = a0;
        orow[fo + 1] = a1;
    } else {
        const float4* w4 = (const float4*)wfc;
        float4 w0 = w4[fo], w1 = w4[fo + 1];
        float s = a0.x * w0.x + a0.y * w0.y + a0.z * w0.z + a0.w * w0.w
                + a1.x * w1.x + a1.y * w1.y + a1.z * w1.z + a1.w * w1.w;
        #pragma unroll
        for (int off = 16; off > 0; off >>= 1)
            s += __shfl_xor_sync(0xffffffff, s, off);
        if (lane == 0) outp[node] = s + bfc[0];
    }
}

// ---------------- launch ----------------
extern "C" void kernel_launch(void* const* d_in, const int* in_sizes, int n_in,
                              void* d_out, int out_size)
{
    const float* x   = (const float*)d_in[0];
    const int*   ei  = (const int*)d_in[1];    // int32 (JAX x64-disabled)
    const float* W1  = (const float*)d_in[2];
    const float* b1  = (const float*)d_in[3];
    const float* W2  = (const float*)d_in[4];
    const float* b2  = (const float*)d_in[5];
    const float* Wfc = (const float*)d_in[6];
    const float* bfc = (const float*)d_in[7];
    float* out = (float*)d_out;

    const int NB_N = (N_NODES + 255) / 256;   // 196
    const int NB_E = (N_EDGES + 255) / 256;   // 3125

    // CSR build + degree norms
    zero_cnt_kernel<<<NB_N, 256>>>();
    count_kernel<<<NB_E, 256>>>(ei);
    scan_blocks_kernel<<<NB_N, 256>>>();      // also computes g_dinv
    scan_bsums_kernel<<<1, 256>>>(NB_N);
    scan_add_kernel<<<NB_N, 256>>>();
    fill_kernel<<<NB_E, 256>>>(ei);

    dim3 ggrid(HID / 64, (N_NODES + 127) / 128);  // (4, 391)

    // layer 1: g_bufA = x @ W1 ; g_bufB = relu(agg(g_bufA) + b1)
    gemm_tf32_kernel<0><<<ggrid, 256>>>(x, W1, N_NODES, FIN);
    agg_kernel<false><<<(N_NODES * 32 + 255) / 256, 256>>>(b1, nullptr, nullptr, nullptr);

    // layer 2: g_bufA = g_bufB @ W2 ; out = relu(agg(g_bufA) + b2) @ Wfc + bfc
    gemm_tf32_kernel<1><<<ggrid, 256>>>(nullptr, W2, N_NODES, HID);
    agg_kernel<true><<<(N_NODES * 32 + 255) / 256, 256>>>(b2, out, Wfc, bfc);
}

// round 11
// speedup vs baseline: 3.3315x; 1.0718x over previous
#include <cuda_runtime.h>
#include <cuda_bf16.h>
#include <cstdint>

#define N_NODES 50000
#define N_EDGES 800000
#define FIN 128
#define HID 256

// ---------------- scratch (no allocation allowed) ----------------
__device__ float g_bufA[N_NODES * HID];   // xw1 / xw2
__device__ float g_bufB[N_NODES * HID];   // h1
__device__ float g_dinv[N_NODES];
__device__ float g_w[N_EDGES];            // per-edge norm = dinv[src]*dinv[dst]
__device__ int   g_cnt[N_NODES];
__device__ int   g_rowptr[N_NODES + 1];
__device__ int   g_cursor[N_NODES];
__device__ int   g_col[N_EDGES];
__device__ int   g_bsums[256];

// ---------------- CSR build ----------------
__global__ void zero_cnt_kernel() {
    int i = blockIdx.x * blockDim.x + threadIdx.x;
    if (i < N_NODES) g_cnt[i] = 0;
}

// 4 edges per thread (N_EDGES % 4 == 0)
__global__ void count_kernel(const int* __restrict__ ei) {
    int t = blockIdx.x * blockDim.x + threadIdx.x;
    int e = t * 4;
    if (e < N_EDGES) {
        int4 d = *(const int4*)(ei + N_EDGES + e);
        atomicAdd(&g_cnt[d.x], 1);
        atomicAdd(&g_cnt[d.y], 1);
        atomicAdd(&g_cnt[d.z], 1);
        atomicAdd(&g_cnt[d.w], 1);
    }
}

// exclusive scan of g_cnt into g_rowptr (per-block) + dinv fold
__global__ void scan_blocks_kernel() {
    __shared__ int sh[256];
    int i = blockIdx.x * 256 + threadIdx.x;
    int v = (i < N_NODES) ? g_cnt[i] : 0;
    if (i < N_NODES) g_dinv[i] = rsqrtf((float)v + 1.0f);  // self-loop included
    sh[threadIdx.x] = v;
    __syncthreads();
    #pragma unroll
    for (int off = 1; off < 256; off <<= 1) {
        int t = (threadIdx.x >= off) ? sh[threadIdx.x - off] : 0;
        __syncthreads();
        sh[threadIdx.x] += t;
        __syncthreads();
    }
    if (i < N_NODES) g_rowptr[i] = sh[threadIdx.x] - v;
    if (threadIdx.x == 255) g_bsums[blockIdx.x] = sh[255];
}

__global__ void scan_bsums_kernel(int nb) {
    __shared__ int sh[256];
    int v = (threadIdx.x < nb) ? g_bsums[threadIdx.x] : 0;
    sh[threadIdx.x] = v;
    __syncthreads();
    #pragma unroll
    for (int off = 1; off < 256; off <<= 1) {
        int t = (threadIdx.x >= off) ? sh[threadIdx.x - off] : 0;
        __syncthreads();
        sh[threadIdx.x] += t;
        __syncthreads();
    }
    if (threadIdx.x < nb) g_bsums[threadIdx.x] = sh[threadIdx.x] - v;
}

__global__ void scan_add_kernel() {
    int i = blockIdx.x * 256 + threadIdx.x;
    if (i < N_NODES) {
        int v = g_rowptr[i] + g_bsums[blockIdx.x];
        g_rowptr[i] = v;
        g_cursor[i] = v;
    }
    if (i == 0) g_rowptr[N_NODES] = N_EDGES;
}

// 4 edges per thread
__global__ void fill_kernel(const int* __restrict__ ei) {
    int t = blockIdx.x * blockDim.x + threadIdx.x;
    int e = t * 4;
    if (e < N_EDGES) {
        int4 s4 = *(const int4*)(ei + e);
        int4 d4 = *(const int4*)(ei + N_EDGES + e);
        {
            int pos = atomicAdd(&g_cursor[d4.x], 1);
            g_col[pos] = s4.x;
            g_w[pos] = g_dinv[s4.x] * g_dinv[d4.x];
        }
        {
            int pos = atomicAdd(&g_cursor[d4.y], 1);
            g_col[pos] = s4.y;
            g_w[pos] = g_dinv[s4.y] * g_dinv[d4.y];
        }
        {
            int pos = atomicAdd(&g_cursor[d4.z], 1);
            g_col[pos] = s4.z;
            g_w[pos] = g_dinv[s4.z] * g_dinv[d4.z];
        }
        {
            int pos = atomicAdd(&g_cursor[d4.w], 1);
            g_col[pos] = s4.w;
            g_w[pos] = g_dinv[s4.w] * g_dinv[d4.w];
        }
    }
}

// ---------------- tf32 tensor-core GEMM, 2-stage cp.async pipeline ----------
// C[M,256] = A[M,K] @ B[K,256]. BM=128, BN=64, BK=16. 256 thr = 8 warps 4x2.
// ASEL: 0 -> A = Aext (x), 1 -> A = g_bufB. C is always g_bufA.
__device__ __forceinline__ uint32_t f2tf32(float f) {
    uint32_t r;
    asm("cvt.rna.tf32.f32 %0, %1;" : "=r"(r) : "f"(f));
    return r;
}

__device__ __forceinline__ void cp_async16(void* smem_dst, const void* gsrc, int src_bytes) {
    uint32_t saddr = (uint32_t)__cvta_generic_to_shared(smem_dst);
    asm volatile("cp.async.cg.shared.global [%0], [%1], 16, %2;"
                 :: "r"(saddr), "l"(gsrc), "r"(src_bytes));
}

template <int ASEL>
__global__ __launch_bounds__(256) void gemm_tf32_kernel(
    const float* __restrict__ Aext, const float* __restrict__ B, int M, int K)
{
    const float* __restrict__ A = (ASEL == 0) ? Aext : (const float*)g_bufB;
    float* __restrict__ C = g_bufA;

    __shared__ float As[2][128][20];  // [stage][m][k], pad 16->20 (80B stride, 16B-aligned)
    __shared__ float Bs[2][16][72];   // [stage][k][n], pad 64->72 (288B stride, 16B-aligned)

    const int tid = threadIdx.x;
    const int warp = tid >> 5, lane = tid & 31;
    const int warp_m = warp & 3, warp_n = warp >> 2;   // 4 x 2
    const int wm = warp_m * 32, wn = warp_n * 32;
    const int groupID = lane >> 2, tig = lane & 3;

    const int bm = blockIdx.y * 128;
    const int bn = blockIdx.x * 64;

    float acc[2][4][4];
    #pragma unroll
    for (int mt = 0; mt < 2; mt++)
        #pragma unroll
        for (int nt = 0; nt < 4; nt++)
            #pragma unroll
            for (int r = 0; r < 4; r++) acc[mt][nt][r] = 0.f;

    // staging indices
    const int ar = tid >> 2;          // 0..63
    const int ac = (tid & 3) * 4;     // 0,4,8,12
    const int br = tid >> 4;          // 0..15
    const int bc = (tid & 15) * 4;    // 0..60

    const int KT = K / 16;

    auto stage = [&](int s, int k0) {
        #pragma unroll
        for (int h = 0; h < 2; h++) {
            int r = ar + h * 64;
            int gr = bm + r;
            cp_async16(&As[s][r][ac], A + (long)gr * K + k0 + ac, (gr < M) ? 16 : 0);
        }
        cp_async16(&Bs[s][br][bc], B + (long)(k0 + br) * HID + bn + bc, 16);
    };

    stage(0, 0);
    asm volatile("cp.async.commit_group;");

    for (int kt = 0; kt < KT; kt++) {
        int buf = kt & 1;
        if (kt + 1 < KT) stage(buf ^ 1, (kt + 1) * 16);
        asm volatile("cp.async.commit_group;");
        asm volatile("cp.async.wait_group 1;");
        __syncthreads();

        #pragma unroll
        for (int ks = 0; ks < 16; ks += 8) {
            uint32_t a[2][4];
            #pragma unroll
            for (int mt = 0; mt < 2; mt++) {
                int r = wm + mt * 16;
                a[mt][0] = f2tf32(As[buf][r + groupID][ks + tig]);
                a[mt][1] = f2tf32(As[buf][r + groupID + 8][ks + tig]);
                a[mt][2] = f2tf32(As[buf][r + groupID][ks + tig + 4]);
                a[mt][3] = f2tf32(As[buf][r + groupID + 8][ks + tig + 4]);
            }
            uint32_t b[4][2];
            #pragma unroll
            for (int nt = 0; nt < 4; nt++) {
                int c = wn + nt * 8 + groupID;
                b[nt][0] = f2tf32(Bs[buf][ks + tig][c]);
                b[nt][1] = f2tf32(Bs[buf][ks + tig + 4][c]);
            }
            #pragma unroll
            for (int mt = 0; mt < 2; mt++)
                #pragma unroll
                for (int nt = 0; nt < 4; nt++) {
                    asm volatile(
                        "mma.sync.aligned.m16n8k8.row.col.f32.tf32.tf32.f32 "
                        "{%0,%1,%2,%3}, {%4,%5,%6,%7}, {%8,%9}, {%0,%1,%2,%3};"
                        : "+f"(acc[mt][nt][0]), "+f"(acc[mt][nt][1]),
                          "+f"(acc[mt][nt][2]), "+f"(acc[mt][nt][3])
                        : "r"(a[mt][0]), "r"(a[mt][1]), "r"(a[mt][2]), "r"(a[mt][3]),
                          "r"(b[nt][0]), "r"(b[nt][1]));
                }
        }
        __syncthreads();
    }

    // epilogue
    #pragma unroll
    for (int mt = 0; mt < 2; mt++) {
        #pragma unroll
        for (int nt = 0; nt < 4; nt++) {
            int r0 = bm + wm + mt * 16 + groupID;
            int c = bn + wn + nt * 8 + tig * 2;
            if (r0 < M) {
                float2 v = make_float2(acc[mt][nt][0], acc[mt][nt][1]);
                *(float2*)(C + (long)r0 * HID + c) = v;
            }
            if (r0 + 8 < M) {
                float2 v = make_float2(acc[mt][nt][2], acc[mt][nt][3]);
                *(float2*)(C + (long)(r0 + 8) * HID + c) = v;
            }
        }
    }
}

// ---------------- aggregation: one warp per node, 8 contiguous feats/thread --
// in = g_bufA. out[node,:] = relu( sum_in w*in[src,:] + dinv^2*in[node,:] + bias )
// FUSE_FC=false: write to g_bufB.  FUSE_FC=true: dot with Wfc -> scalar outp[node].
template <bool FUSE_FC>
__global__ __launch_bounds__(256) void agg_kernel(
    const float* __restrict__ bias,
    float* __restrict__ outp,
    const float* __restrict__ wfc, const float* __restrict__ bfc)
{
    const float* __restrict__ in = (const float*)g_bufA;

    int warp = (blockIdx.x * blockDim.x + threadIdx.x) >> 5;
    int lane = threadIdx.x & 31;
    if (warp >= N_NODES) return;
    const int node = warp;
    const int start = g_rowptr[node];
    const int end   = g_rowptr[node + 1];
    const float di = g_dinv[node];
    const float selfw = di * di;

    const int fo = lane * 2;  // float4 index within 64-float4 row

    float4 a0, a1;
    {
        const float4* row = (const float4*)(in + (long)node * HID);
        float4 v0 = row[fo], v1 = row[fo + 1];
        a0.x = selfw * v0.x; a0.y = selfw * v0.y; a0.z = selfw * v0.z; a0.w = selfw * v0.w;
        a1.x = selfw * v1.x; a1.y = selfw * v1.y; a1.z = selfw * v1.z; a1.w = selfw * v1.w;
    }

    for (int e0 = start; e0 < end; e0 += 32) {
        int e = e0 + lane;
        int src = 0; float w = 0.f;
        if (e < end) { src = g_col[e]; w = g_w[e]; }
        int cnt = min(32, end - e0);
        int j = 0;
        for (; j + 4 <= cnt; j += 4) {
            int   s0 = __shfl_sync(0xffffffff, src, j);
            int   s1 = __shfl_sync(0xffffffff, src, j + 1);
            int   s2 = __shfl_sync(0xffffffff, src, j + 2);
            int   s3 = __shfl_sync(0xffffffff, src, j + 3);
            float w0 = __shfl_sync(0xffffffff, w, j);
            float w1 = __shfl_sync(0xffffffff, w, j + 1);
            float w2 = __shfl_sync(0xffffffff, w, j + 2);
            float w3 = __shfl_sync(0xffffffff, w, j + 3);
            const float4* r0 = (const float4*)(in + (long)s0 * HID);
            const float4* r1 = (const float4*)(in + (long)s1 * HID);
            const float4* r2 = (const float4*)(in + (long)s2 * HID);
            const float4* r3 = (const float4*)(in + (long)s3 * HID);
            float4 p0 = r0[fo], q0 = r0[fo + 1];
            float4 p1 = r1[fo], q1 = r1[fo + 1];
            float4 p2 = r2[fo], q2 = r2[fo + 1];
            float4 p3 = r3[fo], q3 = r3[fo + 1];
            a0.x += w0 * p0.x; a0.y += w0 * p0.y; a0.z += w0 * p0.z; a0.w += w0 * p0.w;
            a1.x += w0 * q0.x; a1.y += w0 * q0.y; a1.z += w0 * q0.z; a1.w += w0 * q0.w;
            a0.x += w1 * p1.x; a0.y += w1 * p1.y; a0.z += w1 * p1.z; a0.w += w1 * p1.w;
            a1.x += w1 * q1.x; a1.y += w1 * q1.y; a1.z += w1 * q1.z; a1.w += w1 * q1.w;
            a0.x += w2 * p2.x; a0.y += w2 * p2.y; a0.z += w2 * p2.z; a0.w += w2 * p2.w;
            a1.x += w2 * q2.x; a1.y += w2 * q2.y; a1.z += w2 * q2.z; a1.w += w2 * q2.w;
            a0.x += w3 * p3.x; a0.y += w3 * p3.y; a0.z += w3 * p3.z; a0.w += w3 * p3.w;
            a1.x += w3 * q3.x; a1.y += w3 * q3.y; a1.z += w3 * q3.z; a1.w += w3 * q3.w;
        }
        for (; j < cnt; j++) {
            int   s  = __shfl_sync(0xffffffff, src, j);
            float ww = __shfl_sync(0xffffffff, w, j);
            const float4* row = (const float4*)(in + (long)s * HID);
            float4 v0 = row[fo], v1 = row[fo + 1];
            a0.x += ww * v0.x; a0.y += ww * v0.y; a0.z += ww * v0.z; a0.w += ww * v0.w;
            a1.x += ww * v1.x; a1.y += ww * v1.y; a1.z += ww * v1.z; a1.w += ww * v1.w;
        }
    }

    {
        const float4* b4 = (const float4*)bias;
        float4 b0 = b4[fo], b1v = b4[fo + 1];
        a0.x = fmaxf(a0.x + b0.x, 0.f);  a0.y = fmaxf(a0.y + b0.y, 0.f);
        a0.z = fmaxf(a0.z + b0.z, 0.f);  a0.w = fmaxf(a0.w + b0.w, 0.f);
        a1.x = fmaxf(a1.x + b1v.x, 0.f); a1.y = fmaxf(a1.y + b1v.y, 0.f);
        a1.z = fmaxf(a1.z + b1v.z, 0.f); a1.w = fmaxf(a1.w + b1v.w, 0.f);
    }

    if (!FUSE_FC) {
        float4* orow = (float4*)(g_bufB + (long)node * HID);
        orow[fo] = a0;
        orow[fo + 1] = a1;
    } else {
        const float4* w4 = (const float4*)wfc;
        float4 w0 = w4[fo], w1 = w4[fo + 1];
        float s = a0.x * w0.x + a0.y * w0.y + a0.z * w0.z + a0.w * w0.w
                + a1.x * w1.x + a1.y * w1.y + a1.z * w1.z + a1.w * w1.w;
        #pragma unroll
        for (int off = 16; off > 0; off >>= 1)
            s += __shfl_xor_sync(0xffffffff, s, off);
        if (lane == 0) outp[node] = s + bfc[0];
    }
}

// ---------------- launch ----------------
extern "C" void kernel_launch(void* const* d_in, const int* in_sizes, int n_in,
                              void* d_out, int out_size)
{
    const float* x   = (const float*)d_in[0];
    const int*   ei  = (const int*)d_in[1];    // int32 (JAX x64-disabled)
    const float* W1  = (const float*)d_in[2];
    const float* b1  = (const float*)d_in[3];
    const float* W2  = (const float*)d_in[4];
    const float* b2  = (const float*)d_in[5];
    const float* Wfc = (const float*)d_in[6];
    const float* bfc = (const float*)d_in[7];
    float* out = (float*)d_out;

    const int NB_N  = (N_NODES + 255) / 256;        // 196
    const int NB_E4 = (N_EDGES / 4 + 255) / 256;    // 782

    dim3 ggrid(HID / 64, (N_NODES + 127) / 128);    // (4, 391)

    // CSR build; gemm1 interleaved (independent of CSR) at launch #4 for profiling
    zero_cnt_kernel<<<NB_N, 256>>>();
    count_kernel<<<NB_E4, 256>>>(ei);
    scan_blocks_kernel<<<NB_N, 256>>>();            // also computes g_dinv
    gemm_tf32_kernel<0><<<ggrid, 256>>>(x, W1, N_NODES, FIN);   // layer-1 GEMM
    scan_bsums_kernel<<<1, 256>>>(NB_N);
    scan_add_kernel<<<NB_N, 256>>>();
    fill_kernel<<<NB_E4, 256>>>(ei);

    // layer 1 aggregation: g_bufB = relu(agg(g_bufA) + b1)
    agg_kernel<false><<<(N_NODES * 32 + 255) / 256, 256>>>(b1, nullptr, nullptr, nullptr);

    // layer 2: g_bufA = g_bufB @ W2 ; out = relu(agg(g_bufA) + b2) @ Wfc + bfc
    gemm_tf32_kernel<1><<<ggrid, 256>>>(nullptr, W2, N_NODES, HID);
    agg_kernel<true><<<(N_NODES * 32 + 255) / 256, 256>>>(b2, out, Wfc, bfc);
}

// round 13
// speedup vs baseline: 4.7351x; 1.4213x over previous
#include <cuda_runtime.h>
#include <cuda_fp16.h>
#include <cstdint>

#define N_NODES 50000
#define N_EDGES 800000
#define FIN 128
#define HID 256

// ---------------- scratch (no allocation allowed) ----------------
__device__ __half g_bufA[N_NODES * HID];  // xw1 / xw2 (fp16)
__device__ __half g_bufB[N_NODES * HID];  // h1 (fp16)
__device__ float g_dinv[N_NODES];
__device__ float g_w[N_EDGES];
__device__ int   g_cnt[N_NODES];
__device__ int   g_rowptr[N_NODES + 1];
__device__ int   g_cursor[N_NODES];
__device__ int   g_col[N_EDGES];
__device__ int   g_bsums[256];

// ---------------- CSR build ----------------
__global__ void zero_cnt_kernel() {
    int i = blockIdx.x * blockDim.x + threadIdx.x;
    if (i < N_NODES) g_cnt[i] = 0;
}

__global__ void count_kernel(const int* __restrict__ ei) {
    int t = blockIdx.x * blockDim.x + threadIdx.x;
    int e = t * 4;
    if (e < N_EDGES) {
        int4 d = *(const int4*)(ei + N_EDGES + e);
        atomicAdd(&g_cnt[d.x], 1);
        atomicAdd(&g_cnt[d.y], 1);
        atomicAdd(&g_cnt[d.z], 1);
        atomicAdd(&g_cnt[d.w], 1);
    }
}

__global__ void scan_blocks_kernel() {
    __shared__ int sh[256];
    int i = blockIdx.x * 256 + threadIdx.x;
    int v = (i < N_NODES) ? g_cnt[i] : 0;
    if (i < N_NODES) g_dinv[i] = rsqrtf((float)v + 1.0f);
    sh[threadIdx.x] = v;
    __syncthreads();
    #pragma unroll
    for (int off = 1; off < 256; off <<= 1) {
        int t = (threadIdx.x >= off) ? sh[threadIdx.x - off] : 0;
        __syncthreads();
        sh[threadIdx.x] += t;
        __syncthreads();
    }
    if (i < N_NODES) g_rowptr[i] = sh[threadIdx.x] - v;
    if (threadIdx.x == 255) g_bsums[blockIdx.x] = sh[255];
}

__global__ void scan_bsums_kernel(int nb) {
    __shared__ int sh[256];
    int v = (threadIdx.x < nb) ? g_bsums[threadIdx.x] : 0;
    sh[threadIdx.x] = v;
    __syncthreads();
    #pragma unroll
    for (int off = 1; off < 256; off <<= 1) {
        int t = (threadIdx.x >= off) ? sh[threadIdx.x - off] : 0;
        __syncthreads();
        sh[threadIdx.x] += t;
        __syncthreads();
    }
    if (threadIdx.x < nb) g_bsums[threadIdx.x] = sh[threadIdx.x] - v;
}

__global__ void scan_add_kernel() {
    int i = blockIdx.x * 256 + threadIdx.x;
    if (i < N_NODES) {
        int v = g_rowptr[i] + g_bsums[blockIdx.x];
        g_rowptr[i] = v;
        g_cursor[i] = v;
    }
    if (i == 0) g_rowptr[N_NODES] = N_EDGES;
}

__global__ void fill_kernel(const int* __restrict__ ei) {
    int t = blockIdx.x * blockDim.x + threadIdx.x;
    int e = t * 4;
    if (e < N_EDGES) {
        int4 s4 = *(const int4*)(ei + e);
        int4 d4 = *(const int4*)(ei + N_EDGES + e);
        { int p = atomicAdd(&g_cursor[d4.x], 1); g_col[p] = s4.x; g_w[p] = g_dinv[s4.x] * g_dinv[d4.x]; }
        { int p = atomicAdd(&g_cursor[d4.y], 1); g_col[p] = s4.y; g_w[p] = g_dinv[s4.y] * g_dinv[d4.y]; }
        { int p = atomicAdd(&g_cursor[d4.z], 1); g_col[p] = s4.z; g_w[p] = g_dinv[s4.z] * g_dinv[d4.z]; }
        { int p = atomicAdd(&g_cursor[d4.w], 1); g_col[p] = s4.w; g_w[p] = g_dinv[s4.w] * g_dinv[d4.w]; }
    }
}

// ---------------- helpers ----------------
__device__ __forceinline__ uint32_t f2tf32(float f) {
    uint32_t r;
    asm("cvt.rna.tf32.f32 %0, %1;" : "=r"(r) : "f"(f));
    return r;
}

__device__ __forceinline__ void cp_async16(void* smem_dst, const void* gsrc, int src_bytes) {
    uint32_t saddr = (uint32_t)__cvta_generic_to_shared(smem_dst);
    asm volatile("cp.async.cg.shared.global [%0], [%1], 16, %2;"
                 :: "r"(saddr), "l"(gsrc), "r"(src_bytes));
}

// ---------------- GEMM1: tf32, C(fp16)[M,256] = x[M,128] @ W1[128,256] -----
__global__ __launch_bounds__(256) void gemm_tf32_kernel(
    const float* __restrict__ A, const float* __restrict__ B, int M, int K)
{
    __half* __restrict__ C = g_bufA;

    __shared__ float As[2][128][20];
    __shared__ float Bs[2][16][72];

    const int tid = threadIdx.x;
    const int warp = tid >> 5, lane = tid & 31;
    const int warp_m = warp & 3, warp_n = warp >> 2;
    const int wm = warp_m * 32, wn = warp_n * 32;
    const int g = lane >> 2, t = lane & 3;

    const int bm = blockIdx.y * 128;
    const int bn = blockIdx.x * 64;

    float acc[2][4][4];
    #pragma unroll
    for (int mt = 0; mt < 2; mt++)
        #pragma unroll
        for (int nt = 0; nt < 4; nt++)
            #pragma unroll
            for (int r = 0; r < 4; r++) acc[mt][nt][r] = 0.f;

    const int ar = tid >> 2;
    const int ac = (tid & 3) * 4;
    const int br = tid >> 4;
    const int bc = (tid & 15) * 4;

    const int KT = K / 16;

    auto stage = [&](int s, int k0) {
        #pragma unroll
        for (int h = 0; h < 2; h++) {
            int r = ar + h * 64;
            int gr = bm + r;
            cp_async16(&As[s][r][ac], A + (long)gr * K + k0 + ac, (gr < M) ? 16 : 0);
        }
        cp_async16(&Bs[s][br][bc], B + (long)(k0 + br) * HID + bn + bc, 16);
    };

    stage(0, 0);
    asm volatile("cp.async.commit_group;");

    for (int kt = 0; kt < KT; kt++) {
        int buf = kt & 1;
        if (kt + 1 < KT) stage(buf ^ 1, (kt + 1) * 16);
        asm volatile("cp.async.commit_group;");
        asm volatile("cp.async.wait_group 1;");
        __syncthreads();

        #pragma unroll
        for (int ks = 0; ks < 16; ks += 8) {
            uint32_t a[2][4];
            #pragma unroll
            for (int mt = 0; mt < 2; mt++) {
                int r = wm + mt * 16;
                a[mt][0] = f2tf32(As[buf][r + g][ks + t]);
                a[mt][1] = f2tf32(As[buf][r + g + 8][ks + t]);
                a[mt][2] = f2tf32(As[buf][r + g][ks + t + 4]);
                a[mt][3] = f2tf32(As[buf][r + g + 8][ks + t + 4]);
            }
            uint32_t b[4][2];
            #pragma unroll
            for (int nt = 0; nt < 4; nt++) {
                int c = wn + nt * 8 + g;
                b[nt][0] = f2tf32(Bs[buf][ks + t][c]);
                b[nt][1] = f2tf32(Bs[buf][ks + t + 4][c]);
            }
            #pragma unroll
            for (int mt = 0; mt < 2; mt++)
                #pragma unroll
                for (int nt = 0; nt < 4; nt++) {
                    asm volatile(
                        "mma.sync.aligned.m16n8k8.row.col.f32.tf32.tf32.f32 "
                        "{%0,%1,%2,%3}, {%4,%5,%6,%7}, {%8,%9}, {%0,%1,%2,%3};"
                        : "+f"(acc[mt][nt][0]), "+f"(acc[mt][nt][1]),
                          "+f"(acc[mt][nt][2]), "+f"(acc[mt][nt][3])
                        : "r"(a[mt][0]), "r"(a[mt][1]), "r"(a[mt][2]), "r"(a[mt][3]),
                          "r"(b[nt][0]), "r"(b[nt][1]));
                }
        }
        __syncthreads();
    }

    #pragma unroll
    for (int mt = 0; mt < 2; mt++) {
        #pragma unroll
        for (int nt = 0; nt < 4; nt++) {
            int r0 = bm + wm + mt * 16 + g;
            int c = bn + wn + nt * 8 + t * 2;
            if (r0 < M)
                *(half2*)(C + (long)r0 * HID + c) = __floats2half2_rn(acc[mt][nt][0], acc[mt][nt][1]);
            if (r0 + 8 < M)
                *(half2*)(C + (long)(r0 + 8) * HID + c) = __floats2half2_rn(acc[mt][nt][2], acc[mt][nt][3]);
        }
    }
}

// ---------------- GEMM2: fp16 HMMA, C(fp16)[M,256] = h1(fp16)[M,256] @ W2 ---
// BM=128, BN=64, BK=32. mma m16n8k16.f16 with fp32 accum.
// W2 (fp32) converted to fp16 at staging via register-prefetch pipeline.
__global__ __launch_bounds__(256) void gemm_f16_kernel(const float* __restrict__ B)
{
    const __half* __restrict__ A = g_bufB;
    __half* __restrict__ C = g_bufA;
    const int M = N_NODES, K = HID;

    __shared__ __half As[2][128][40];  // 80B row stride: 16B aligned, LDS conflict-free
    __shared__ __half Bs[2][64][40];   // [n][k] layout for col-major B fragments

    const int tid = threadIdx.x;
    const int warp = tid >> 5, lane = tid & 31;
    const int warp_m = warp & 3, warp_n = warp >> 2;
    const int wm = warp_m * 32, wn = warp_n * 32;
    const int g = lane >> 2, t = lane & 3;
    const int bm = blockIdx.y * 128, bn = blockIdx.x * 64;

    float acc[2][4][4];
    #pragma unroll
    for (int mt = 0; mt < 2; mt++)
        #pragma unroll
        for (int nt = 0; nt < 4; nt++)
            #pragma unroll
            for (int r = 0; r < 4; r++) acc[mt][nt][r] = 0.f;

    const int ar = tid >> 1;            // 0..127
    const int ahalf = (tid & 1) * 16;   // halves offset within 32-half row
    const int bnn = tid & 63;           // n within tile
    const int bkg = tid >> 6;           // 0..3 (8 k each)

    const int KT = K / 32;  // 8

    auto stageA = [&](int s, int k0) {
        int gr = bm + ar;
        const __half* gsrc = A + (long)gr * HID + k0 + ahalf;
        int nb = (gr < M) ? 16 : 0;
        cp_async16(&As[s][ar][ahalf], gsrc, nb);
        cp_async16(&As[s][ar][ahalf + 8], gsrc + 8, nb);
    };

    float rB[8];
    auto ldgB = [&](int k0) {
        #pragma unroll
        for (int j = 0; j < 8; j++)
            rB[j] = B[(long)(k0 + bkg * 8 + j) * HID + bn + bnn];
    };
    auto stsB = [&](int s) {
        #pragma unroll
        for (int j = 0; j < 4; j++)
            *(half2*)&Bs[s][bnn][bkg * 8 + 2 * j] = __floats2half2_rn(rB[2 * j], rB[2 * j + 1]);
    };

    stageA(0, 0);
    asm volatile("cp.async.commit_group;");
    ldgB(0);
    stsB(0);

    for (int kt = 0; kt < KT; kt++) {
        int buf = kt & 1;
        if (kt + 1 < KT) stageA(buf ^ 1, (kt + 1) * 32);
        asm volatile("cp.async.commit_group;");
        if (kt + 1 < KT) ldgB((kt + 1) * 32);
        asm volatile("cp.async.wait_group 1;");
        __syncthreads();

        #pragma unroll
        for (int ks = 0; ks < 2; ks++) {
            const int kc = ks * 16 + 2 * t;
            uint32_t a[2][4];
            #pragma unroll
            for (int mt = 0; mt < 2; mt++) {
                int r = wm + mt * 16;
                a[mt][0] = *(const uint32_t*)&As[buf][r + g][kc];
                a[mt][1] = *(const uint32_t*)&As[buf][r + g + 8][kc];
                a[mt][2] = *(const uint32_t*)&As[buf][r + g][kc + 8];
                a[mt][3] = *(const uint32_t*)&As[buf][r + g + 8][kc + 8];
            }
            uint32_t b[4][2];
            #pragma unroll
            for (int nt = 0; nt < 4; nt++) {
                int c = wn + nt * 8 + g;
                b[nt][0] = *(const uint32_t*)&Bs[buf][c][kc];
                b[nt][1] = *(const uint32_t*)&Bs[buf][c][kc + 8];
            }
            #pragma unroll
            for (int mt = 0; mt < 2; mt++)
                #pragma unroll
                for (int nt = 0; nt < 4; nt++) {
                    asm volatile(
                        "mma.sync.aligned.m16n8k16.row.col.f32.f16.f16.f32 "
                        "{%0,%1,%2,%3}, {%4,%5,%6,%7}, {%8,%9}, {%0,%1,%2,%3};"
                        : "+f"(acc[mt][nt][0]), "+f"(acc[mt][nt][1]),
                          "+f"(acc[mt][nt][2]), "+f"(acc[mt][nt][3])
                        : "r"(a[mt][0]), "r"(a[mt][1]), "r"(a[mt][2]), "r"(a[mt][3]),
                          "r"(b[nt][0]), "r"(b[nt][1]));
                }
        }
        if (kt + 1 < KT) stsB(buf ^ 1);
        __syncthreads();
    }

    #pragma unroll
    for (int mt = 0; mt < 2; mt++) {
        #pragma unroll
        for (int nt = 0; nt < 4; nt++) {
            int r0 = bm + wm + mt * 16 + g;
            int c = bn + wn + nt * 8 + t * 2;
            if (r0 < M)
                *(half2*)(C + (long)r0 * HID + c) = __floats2half2_rn(acc[mt][nt][0], acc[mt][nt][1]);
            if (r0 + 8 < M)
                *(half2*)(C + (long)(r0 + 8) * HID + c) = __floats2half2_rn(acc[mt][nt][2], acc[mt][nt][3]);
        }
    }
}

// ---------------- aggregation: fp16 rows, fp32 accum ------------------------
// in = g_bufA (fp16). Each lane owns 8 feats = one uint4 (16B) per row.
__device__ __forceinline__ void acc8(float* acc, uint4 v, float w) {
    float2 f0 = __half22float2(*(__half2*)&v.x);
    float2 f1 = __half22float2(*(__half2*)&v.y);
    float2 f2 = __half22float2(*(__half2*)&v.z);
    float2 f3 = __half22float2(*(__half2*)&v.w);
    acc[0] += w * f0.x; acc[1] += w * f0.y;
    acc[2] += w * f1.x; acc[3] += w * f1.y;
    acc[4] += w * f2.x; acc[5] += w * f2.y;
    acc[6] += w * f3.x; acc[7] += w * f3.y;
}

template <bool FUSE_FC>
__global__ __launch_bounds__(256) void agg_kernel(
    const float* __restrict__ bias,
    float* __restrict__ outp,
    const float* __restrict__ wfc, const float* __restrict__ bfc)
{
    const __half* __restrict__ in = g_bufA;

    int warpid = (blockIdx.x * blockDim.x + threadIdx.x) >> 5;
    int lane = threadIdx.x & 31;
    if (warpid >= N_NODES) return;
    const int node = warpid;
    const int start = g_rowptr[node];
    const int end   = g_rowptr[node + 1];
    const float di = g_dinv[node];
    const float selfw = di * di;

    float acc[8];
    #pragma unroll
    for (int k = 0; k < 8; k++) acc[k] = 0.f;
    acc8(acc, ((const uint4*)(in + (long)node * HID))[lane], selfw);

    for (int e0 = start; e0 < end; e0 += 32) {
        int e = e0 + lane;
        int src = 0; float w = 0.f;
        if (e < end) { src = g_col[e]; w = g_w[e]; }
        int cnt = min(32, end - e0);
        int j = 0;
        for (; j + 4 <= cnt; j += 4) {
            int   s0 = __shfl_sync(0xffffffff, src, j);
            int   s1 = __shfl_sync(0xffffffff, src, j + 1);
            int   s2 = __shfl_sync(0xffffffff, src, j + 2);
            int   s3 = __shfl_sync(0xffffffff, src, j + 3);
            float w0 = __shfl_sync(0xffffffff, w, j);
            float w1 = __shfl_sync(0xffffffff, w, j + 1);
            float w2 = __shfl_sync(0xffffffff, w, j + 2);
            float w3 = __shfl_sync(0xffffffff, w, j + 3);
            uint4 v0 = ((const uint4*)(in + (long)s0 * HID))[lane];
            uint4 v1 = ((const uint4*)(in + (long)s1 * HID))[lane];
            uint4 v2 = ((const uint4*)(in + (long)s2 * HID))[lane];
            uint4 v3 = ((const uint4*)(in + (long)s3 * HID))[lane];
            acc8(acc, v0, w0);
            acc8(acc, v1, w1);
            acc8(acc, v2, w2);
            acc8(acc, v3, w3);
        }
        for (; j < cnt; j++) {
            int   s  = __shfl_sync(0xffffffff, src, j);
            float ww = __shfl_sync(0xffffffff, w, j);
            acc8(acc, ((const uint4*)(in + (long)s * HID))[lane], ww);
        }
    }

    // bias + relu (fp32)
    {
        const float4* b4 = (const float4*)bias;
        float4 b0 = b4[lane * 2], b1v = b4[lane * 2 + 1];
        acc[0] = fmaxf(acc[0] + b0.x, 0.f);  acc[1] = fmaxf(acc[1] + b0.y, 0.f);
        acc[2] = fmaxf(acc[2] + b0.z, 0.f);  acc[3] = fmaxf(acc[3] + b0.w, 0.f);
        acc[4] = fmaxf(acc[4] + b1v.x, 0.f); acc[5] = fmaxf(acc[5] + b1v.y, 0.f);
        acc[6] = fmaxf(acc[6] + b1v.z, 0.f); acc[7] = fmaxf(acc[7] + b1v.w, 0.f);
    }

    if (!FUSE_FC) {
        uint4 ov;
        *(half2*)&ov.x = __floats2half2_rn(acc[0], acc[1]);
        *(half2*)&ov.y = __floats2half2_rn(acc[2], acc[3]);
        *(half2*)&ov.z = __floats2half2_rn(acc[4], acc[5]);
        *(half2*)&ov.w = __floats2half2_rn(acc[6], acc[7]);
        ((uint4*)(g_bufB + (long)node * HID))[lane] = ov;
    } else {
        const float4* w4 = (const float4*)wfc;
        float4 w0 = w4[lane * 2], w1 = w4[lane * 2 + 1];
        float s = acc[0] * w0.x + acc[1] * w0.y + acc[2] * w0.z + acc[3] * w0.w
                + acc[4] * w1.x + acc[5] * w1.y + acc[6] * w1.z + acc[7] * w1.w;
        #pragma unroll
        for (int off = 16; off > 0; off >>= 1)
            s += __shfl_xor_sync(0xffffffff, s, off);
        if (lane == 0) outp[node] = s + bfc[0];
    }
}

// ---------------- launch ----------------
extern "C" void kernel_launch(void* const* d_in, const int* in_sizes, int n_in,
                              void* d_out, int out_size)
{
    const float* x   = (const float*)d_in[0];
    const int*   ei  = (const int*)d_in[1];    // int32 (JAX x64-disabled)
    const float* W1  = (const float*)d_in[2];
    const float* b1  = (const float*)d_in[3];
    const float* W2  = (const float*)d_in[4];
    const float* b2  = (const float*)d_in[5];
    const float* Wfc = (const float*)d_in[6];
    const float* bfc = (const float*)d_in[7];
    float* out = (float*)d_out;

    const int NB_N  = (N_NODES + 255) / 256;
    const int NB_E4 = (N_EDGES / 4 + 255) / 256;

    dim3 ggrid(HID / 64, (N_NODES + 127) / 128);  // (4, 391)

    zero_cnt_kernel<<<NB_N, 256>>>();
    count_kernel<<<NB_E4, 256>>>(ei);
    scan_blocks_kernel<<<NB_N, 256>>>();
    gemm_tf32_kernel<<<ggrid, 256>>>(x, W1, N_NODES, FIN);  // slot #4 for ncu
    scan_bsums_kernel<<<1, 256>>>(NB_N);
    scan_add_kernel<<<NB_N, 256>>>();
    fill_kernel<<<NB_E4, 256>>>(ei);

    agg_kernel<false><<<(N_NODES * 32 + 255) / 256, 256>>>(b1, nullptr, nullptr, nullptr);
    gemm_f16_kernel<<<ggrid, 256>>>(W2);
    agg_kernel<true><<<(N_NODES * 32 + 255) / 256, 256>>>(b2, out, Wfc, bfc);
}

// round 17
// speedup vs baseline: 4.7898x; 1.0116x over previous
#include <cuda_runtime.h>
#include <cuda_fp16.h>
#include <cstdint>

#define N_NODES 50000
#define N_EDGES 800000
#define FIN 128
#define HID 256

// ---------------- scratch (no allocation allowed) ----------------
__device__ __half g_bufA[N_NODES * HID];  // xw1 / xw2 (fp16)
__device__ __half g_bufB[N_NODES * HID];  // h1 (fp16)
__device__ float g_dinv[N_NODES];
__device__ float g_w[N_EDGES];
__device__ int   g_cnt[N_NODES];
__device__ int   g_rowptr[N_NODES + 1];
__device__ int   g_cursor[N_NODES];
__device__ int   g_col[N_EDGES];
__device__ int   g_bsums[256];

// Side stream for overlapping gemm1 with CSR build. Created once at process
// start. If creation fails (transient device-busy at load), g_streamOk stays
// false and kernel_launch falls back to stream 0 (serial, still correct).
static cudaStream_t g_s2 = nullptr;
static cudaEvent_t  g_evFork = nullptr, g_evJoin = nullptr;
static bool g_streamOk = false;
static struct StreamInit {
    StreamInit() {
        bool ok = true;
        ok &= (cudaStreamCreateWithFlags(&g_s2, cudaStreamNonBlocking) == cudaSuccess);
        ok &= (cudaEventCreateWithFlags(&g_evFork, cudaEventDisableTiming) == cudaSuccess);
        ok &= (cudaEventCreateWithFlags(&g_evJoin, cudaEventDisableTiming) == cudaSuccess);
        g_streamOk = ok;
    }
} g_streamInit;

// ---------------- CSR build ----------------
__global__ void zero_cnt_kernel() {
    int i = blockIdx.x * blockDim.x + threadIdx.x;
    if (i < N_NODES) g_cnt[i] = 0;
}

__global__ void count_kernel(const int* __restrict__ ei) {
    int t = blockIdx.x * blockDim.x + threadIdx.x;
    int e = t * 4;
    if (e < N_EDGES) {
        int4 d = *(const int4*)(ei + N_EDGES + e);
        atomicAdd(&g_cnt[d.x], 1);
        atomicAdd(&g_cnt[d.y], 1);
        atomicAdd(&g_cnt[d.z], 1);
        atomicAdd(&g_cnt[d.w], 1);
    }
}

__global__ void scan_blocks_kernel() {
    __shared__ int sh[256];
    int i = blockIdx.x * 256 + threadIdx.x;
    int v = (i < N_NODES) ? g_cnt[i] : 0;
    if (i < N_NODES) g_dinv[i] = rsqrtf((float)v + 1.0f);
    sh[threadIdx.x] = v;
    __syncthreads();
    #pragma unroll
    for (int off = 1; off < 256; off <<= 1) {
        int t = (threadIdx.x >= off) ? sh[threadIdx.x - off] : 0;
        __syncthreads();
        sh[threadIdx.x] += t;
        __syncthreads();
    }
    if (i < N_NODES) g_rowptr[i] = sh[threadIdx.x] - v;
    if (threadIdx.x == 255) g_bsums[blockIdx.x] = sh[255];
}

__global__ void scan_bsums_kernel(int nb) {
    __shared__ int sh[256];
    int v = (threadIdx.x < nb) ? g_bsums[threadIdx.x] : 0;
    sh[threadIdx.x] = v;
    __syncthreads();
    #pragma unroll
    for (int off = 1; off < 256; off <<= 1) {
        int t = (threadIdx.x >= off) ? sh[threadIdx.x - off] : 0;
        __syncthreads();
        sh[threadIdx.x] += t;
        __syncthreads();
    }
    if (threadIdx.x < nb) g_bsums[threadIdx.x] = sh[threadIdx.x] - v;
}

__global__ void scan_add_kernel() {
    int i = blockIdx.x * 256 + threadIdx.x;
    if (i < N_NODES) {
        int v = g_rowptr[i] + g_bsums[blockIdx.x];
        g_rowptr[i] = v;
        g_cursor[i] = v;
    }
    if (i == 0) g_rowptr[N_NODES] = N_EDGES;
}

__global__ void fill_kernel(const int* __restrict__ ei) {
    int t = blockIdx.x * blockDim.x + threadIdx.x;
    int e = t * 4;
    if (e < N_EDGES) {
        int4 s4 = *(const int4*)(ei + e);
        int4 d4 = *(const int4*)(ei + N_EDGES + e);
        { int p = atomicAdd(&g_cursor[d4.x], 1); g_col[p] = s4.x; g_w[p] = g_dinv[s4.x] * g_dinv[d4.x]; }
        { int p = atomicAdd(&g_cursor[d4.y], 1); g_col[p] = s4.y; g_w[p] = g_dinv[s4.y] * g_dinv[d4.y]; }
        { int p = atomicAdd(&g_cursor[d4.z], 1); g_col[p] = s4.z; g_w[p] = g_dinv[s4.z] * g_dinv[d4.z]; }
        { int p = atomicAdd(&g_cursor[d4.w], 1); g_col[p] = s4.w; g_w[p] = g_dinv[s4.w] * g_dinv[d4.w]; }
    }
}

// ---------------- helpers ----------------
__device__ __forceinline__ uint32_t f2tf32(float f) {
    uint32_t r;
    asm("cvt.rna.tf32.f32 %0, %1;" : "=r"(r) : "f"(f));
    return r;
}

__device__ __forceinline__ void cp_async16(void* smem_dst, const void* gsrc, int src_bytes) {
    uint32_t saddr = (uint32_t)__cvta_generic_to_shared(smem_dst);
    asm volatile("cp.async.cg.shared.global [%0], [%1], 16, %2;"
                 :: "r"(saddr), "l"(gsrc), "r"(src_bytes));
}

// ---------------- GEMM1: tf32, C(fp16)[M,256] = x[M,128] @ W1[128,256] -----
__global__ __launch_bounds__(256) void gemm_tf32_kernel(
    const float* __restrict__ A, const float* __restrict__ B, int M, int K)
{
    __half* __restrict__ C = g_bufA;

    __shared__ float As[2][128][20];
    __shared__ float Bs[2][16][72];

    const int tid = threadIdx.x;
    const int warp = tid >> 5, lane = tid & 31;
    const int warp_m = warp & 3, warp_n = warp >> 2;
    const int wm = warp_m * 32, wn = warp_n * 32;
    const int g = lane >> 2, t = lane & 3;

    const int bm = blockIdx.y * 128;
    const int bn = blockIdx.x * 64;

    float acc[2][4][4];
    #pragma unroll
    for (int mt = 0; mt < 2; mt++)
        #pragma unroll
        for (int nt = 0; nt < 4; nt++)
            #pragma unroll
            for (int r = 0; r < 4; r++) acc[mt][nt][r] = 0.f;

    const int ar = tid >> 2;
    const int ac = (tid & 3) * 4;
    const int br = tid >> 4;
    const int bc = (tid & 15) * 4;

    const int KT = K / 16;

    auto stage = [&](int s, int k0) {
        #pragma unroll
        for (int h = 0; h < 2; h++) {
            int r = ar + h * 64;
            int gr = bm + r;
            cp_async16(&As[s][r][ac], A + (long)gr * K + k0 + ac, (gr < M) ? 16 : 0);
        }
        cp_async16(&Bs[s][br][bc], B + (long)(k0 + br) * HID + bn + bc, 16);
    };

    stage(0, 0);
    asm volatile("cp.async.commit_group;");

    for (int kt = 0; kt < KT; kt++) {
        int buf = kt & 1;
        if (kt + 1 < KT) stage(buf ^ 1, (kt + 1) * 16);
        asm volatile("cp.async.commit_group;");
        asm volatile("cp.async.wait_group 1;");
        __syncthreads();

        #pragma unroll
        for (int ks = 0; ks < 16; ks += 8) {
            uint32_t a[2][4];
            #pragma unroll
            for (int mt = 0; mt < 2; mt++) {
                int r = wm + mt * 16;
                a[mt][0] = f2tf32(As[buf][r + g][ks + t]);
                a[mt][1] = f2tf32(As[buf][r + g + 8][ks + t]);
                a[mt][2] = f2tf32(As[buf][r + g][ks + t + 4]);
                a[mt][3] = f2tf32(As[buf][r + g + 8][ks + t + 4]);
            }
            uint32_t b[4][2];
            #pragma unroll
            for (int nt = 0; nt < 4; nt++) {
                int c = wn + nt * 8 + g;
                b[nt][0] = f2tf32(Bs[buf][ks + t][c]);
                b[nt][1] = f2tf32(Bs[buf][ks + t + 4][c]);
            }
            #pragma unroll
            for (int mt = 0; mt < 2; mt++)
                #pragma unroll
                for (int nt = 0; nt < 4; nt++) {
                    asm volatile(
                        "mma.sync.aligned.m16n8k8.row.col.f32.tf32.tf32.f32 "
                        "{%0,%1,%2,%3}, {%4,%5,%6,%7}, {%8,%9}, {%0,%1,%2,%3};"
                        : "+f"(acc[mt][nt][0]), "+f"(acc[mt][nt][1]),
                          "+f"(acc[mt][nt][2]), "+f"(acc[mt][nt][3])
                        : "r"(a[mt][0]), "r"(a[mt][1]), "r"(a[mt][2]), "r"(a[mt][3]),
                          "r"(b[nt][0]), "r"(b[nt][1]));
                }
        }
        __syncthreads();
    }

    #pragma unroll
    for (int mt = 0; mt < 2; mt++) {
        #pragma unroll
        for (int nt = 0; nt < 4; nt++) {
            int r0 = bm + wm + mt * 16 + g;
            int c = bn + wn + nt * 8 + t * 2;
            if (r0 < M)
                *(half2*)(C + (long)r0 * HID + c) = __floats2half2_rn(acc[mt][nt][0], acc[mt][nt][1]);
            if (r0 + 8 < M)
                *(half2*)(C + (long)(r0 + 8) * HID + c) = __floats2half2_rn(acc[mt][nt][2], acc[mt][nt][3]);
        }
    }
}

// ---------------- GEMM2: fp16 HMMA, C(fp16)[M,256] = h1(fp16)[M,256] @ W2 ---
__global__ __launch_bounds__(256) void gemm_f16_kernel(const float* __restrict__ B)
{
    const __half* __restrict__ A = g_bufB;
    __half* __restrict__ C = g_bufA;
    const int M = N_NODES, K = HID;

    __shared__ __half As[2][128][40];
    __shared__ __half Bs[2][64][40];

    const int tid = threadIdx.x;
    const int warp = tid >> 5, lane = tid & 31;
    const int warp_m = warp & 3, warp_n = warp >> 2;
    const int wm = warp_m * 32, wn = warp_n * 32;
    const int g = lane >> 2, t = lane & 3;
    const int bm = blockIdx.y * 128, bn = blockIdx.x * 64;

    float acc[2][4][4];
    #pragma unroll
    for (int mt = 0; mt < 2; mt++)
        #pragma unroll
        for (int nt = 0; nt < 4; nt++)
            #pragma unroll
            for (int r = 0; r < 4; r++) acc[mt][nt][r] = 0.f;

    const int ar = tid >> 1;
    const int ahalf = (tid & 1) * 16;
    const int bnn = tid & 63;
    const int bkg = tid >> 6;

    const int KT = K / 32;

    auto stageA = [&](int s, int k0) {
        int gr = bm + ar;
        const __half* gsrc = A + (long)gr * HID + k0 + ahalf;
        int nb = (gr < M) ? 16 : 0;
        cp_async16(&As[s][ar][ahalf], gsrc, nb);
        cp_async16(&As[s][ar][ahalf + 8], gsrc + 8, nb);
    };

    float rB[8];
    auto ldgB = [&](int k0) {
        #pragma unroll
        for (int j = 0; j < 8; j++)
            rB[j] = B[(long)(k0 + bkg * 8 + j) * HID + bn + bnn];
    };
    auto stsB = [&](int s) {
        #pragma unroll
        for (int j = 0; j < 4; j++)
            *(half2*)&Bs[s][bnn][bkg * 8 + 2 * j] = __floats2half2_rn(rB[2 * j], rB[2 * j + 1]);
    };

    stageA(0, 0);
    asm volatile("cp.async.commit_group;");
    ldgB(0);
    stsB(0);

    for (int kt = 0; kt < KT; kt++) {
        int buf = kt & 1;
        if (kt + 1 < KT) stageA(buf ^ 1, (kt + 1) * 32);
        asm volatile("cp.async.commit_group;");
        if (kt + 1 < KT) ldgB((kt + 1) * 32);
        asm volatile("cp.async.wait_group 1;");
        __syncthreads();

        #pragma unroll
        for (int ks = 0; ks < 2; ks++) {
            const int kc = ks * 16 + 2 * t;
            uint32_t a[2][4];
            #pragma unroll
            for (int mt = 0; mt < 2; mt++) {
                int r = wm + mt * 16;
                a[mt][0] = *(const uint32_t*)&As[buf][r + g][kc];
                a[mt][1] = *(const uint32_t*)&As[buf][r + g + 8][kc];
                a[mt][2] = *(const uint32_t*)&As[buf][r + g][kc + 8];
                a[mt][3] = *(const uint32_t*)&As[buf][r + g + 8][kc + 8];
            }
            uint32_t b[4][2];
            #pragma unroll
            for (int nt = 0; nt < 4; nt++) {
                int c = wn + nt * 8 + g;
                b[nt][0] = *(const uint32_t*)&Bs[buf][c][kc];
                b[nt][1] = *(const uint32_t*)&Bs[buf][c][kc + 8];
            }
            #pragma unroll
            for (int mt = 0; mt < 2; mt++)
                #pragma unroll
                for (int nt = 0; nt < 4; nt++) {
                    asm volatile(
                        "mma.sync.aligned.m16n8k16.row.col.f32.f16.f16.f32 "
                        "{%0,%1,%2,%3}, {%4,%5,%6,%7}, {%8,%9}, {%0,%1,%2,%3};"
                        : "+f"(acc[mt][nt][0]), "+f"(acc[mt][nt][1]),
                          "+f"(acc[mt][nt][2]), "+f"(acc[mt][nt][3])
                        : "r"(a[mt][0]), "r"(a[mt][1]), "r"(a[mt][2]), "r"(a[mt][3]),
                          "r"(b[nt][0]), "r"(b[nt][1]));
                }
        }
        if (kt + 1 < KT) stsB(buf ^ 1);
        __syncthreads();
    }

    #pragma unroll
    for (int mt = 0; mt < 2; mt++) {
        #pragma unroll
        for (int nt = 0; nt < 4; nt++) {
            int r0 = bm + wm + mt * 16 + g;
            int c = bn + wn + nt * 8 + t * 2;
            if (r0 < M)
                *(half2*)(C + (long)r0 * HID + c) = __floats2half2_rn(acc[mt][nt][0], acc[mt][nt][1]);
            if (r0 + 8 < M)
                *(half2*)(C + (long)(r0 + 8) * HID + c) = __floats2half2_rn(acc[mt][nt][2], acc[mt][nt][3]);
        }
    }
}

// ---------------- aggregation: fp16 rows, fp32 accum ------------------------
__device__ __forceinline__ void acc8(float* acc, uint4 v, float w) {
    float2 f0 = __half22float2(*(__half2*)&v.x);
    float2 f1 = __half22float2(*(__half2*)&v.y);
    float2 f2 = __half22float2(*(__half2*)&v.z);
    float2 f3 = __half22float2(*(__half2*)&v.w);
    acc[0] += w * f0.x; acc[1] += w * f0.y;
    acc[2] += w * f1.x; acc[3] += w * f1.y;
    acc[4] += w * f2.x; acc[5] += w * f2.y;
    acc[6] += w * f3.x; acc[7] += w * f3.y;
}

template <bool FUSE_FC>
__global__ __launch_bounds__(256) void agg_kernel(
    const float* __restrict__ bias,
    float* __restrict__ outp,
    const float* __restrict__ wfc, const float* __restrict__ bfc)
{
    const __half* __restrict__ in = g_bufA;

    int warpid = (blockIdx.x * blockDim.x + threadIdx.x) >> 5;
    int lane = threadIdx.x & 31;
    if (warpid >= N_NODES) return;
    const int node = warpid;
    const int start = g_rowptr[node];
    const int end   = g_rowptr[node + 1];
    const float di = g_dinv[node];
    const float selfw = di * di;

    float acc[8];
    #pragma unroll
    for (int k = 0; k < 8; k++) acc[k] = 0.f;
    acc8(acc, ((const uint4*)(in + (long)node * HID))[lane], selfw);

    for (int e0 = start; e0 < end; e0 += 32) {
        int e = e0 + lane;
        int src = 0; float w = 0.f;
        if (e < end) { src = g_col[e]; w = g_w[e]; }
        int cnt = min(32, end - e0);
        int j = 0;
        for (; j + 4 <= cnt; j += 4) {
            int   s0 = __shfl_sync(0xffffffff, src, j);
            int   s1 = __shfl_sync(0xffffffff, src, j + 1);
            int   s2 = __shfl_sync(0xffffffff, src, j + 2);
            int   s3 = __shfl_sync(0xffffffff, src, j + 3);
            float w0 = __shfl_sync(0xffffffff, w, j);
            float w1 = __shfl_sync(0xffffffff, w, j + 1);
            float w2 = __shfl_sync(0xffffffff, w, j + 2);
            float w3 = __shfl_sync(0xffffffff, w, j + 3);
            uint4 v0 = ((const uint4*)(in + (long)s0 * HID))[lane];
            uint4 v1 = ((const uint4*)(in + (long)s1 * HID))[lane];
            uint4 v2 = ((const uint4*)(in + (long)s2 * HID))[lane];
            uint4 v3 = ((const uint4*)(in + (long)s3 * HID))[lane];
            acc8(acc, v0, w0);
            acc8(acc, v1, w1);
            acc8(acc, v2, w2);
            acc8(acc, v3, w3);
        }
        for (; j < cnt; j++) {
            int   s  = __shfl_sync(0xffffffff, src, j);
            float ww = __shfl_sync(0xffffffff, w, j);
            acc8(acc, ((const uint4*)(in + (long)s * HID))[lane], ww);
        }
    }

    {
        const float4* b4 = (const float4*)bias;
        float4 b0 = b4[lane * 2], b1v = b4[lane * 2 + 1];
        acc[0] = fmaxf(acc[0] + b0.x, 0.f);  acc[1] = fmaxf(acc[1] + b0.y, 0.f);
        acc[2] = fmaxf(acc[2] + b0.z, 0.f);  acc[3] = fmaxf(acc[3] + b0.w, 0.f);
        acc[4] = fmaxf(acc[4] + b1v.x, 0.f); acc[5] = fmaxf(acc[5] + b1v.y, 0.f);
        acc[6] = fmaxf(acc[6] + b1v.z, 0.f); acc[7] = fmaxf(acc[7] + b1v.w, 0.f);
    }

    if (!FUSE_FC) {
        uint4 ov;
        *(half2*)&ov.x = __floats2half2_rn(acc[0], acc[1]);
        *(half2*)&ov.y = __floats2half2_rn(acc[2], acc[3]);
        *(half2*)&ov.z = __floats2half2_rn(acc[4], acc[5]);
        *(half2*)&ov.w = __floats2half2_rn(acc[6], acc[7]);
        ((uint4*)(g_bufB + (long)node * HID))[lane] = ov;
    } else {
        const float4* w4 = (const float4*)wfc;
        float4 w0 = w4[lane * 2], w1 = w4[lane * 2 + 1];
        float s = acc[0] * w0.x + acc[1] * w0.y + acc[2] * w0.z + acc[3] * w0.w
                + acc[4] * w1.x + acc[5] * w1.y + acc[6] * w1.z + acc[7] * w1.w;
        #pragma unroll
        for (int off = 16; off > 0; off >>= 1)
            s += __shfl_xor_sync(0xffffffff, s, off);
        if (lane == 0) outp[node] = s + bfc[0];
    }
}

// ---------------- launch ----------------
extern "C" void kernel_launch(void* const* d_in, const int* in_sizes, int n_in,
                              void* d_out, int out_size)
{
    const float* x   = (const float*)d_in[0];
    const int*   ei  = (const int*)d_in[1];    // int32 (JAX x64-disabled)
    const float* W1  = (const float*)d_in[2];
    const float* b1  = (const float*)d_in[3];
    const float* W2  = (const float*)d_in[4];
    const float* b2  = (const float*)d_in[5];
    const float* Wfc = (const float*)d_in[6];
    const float* bfc = (const float*)d_in[7];
    float* out = (float*)d_out;

    const int NB_N  = (N_NODES + 255) / 256;
    const int NB_E4 = (N_EDGES / 4 + 255) / 256;

    dim3 ggrid(HID / 64, (N_NODES + 127) / 128);  // (4, 391)

    if (g_streamOk) {
        // Fork: gemm1 (independent of CSR) runs on side stream g_s2.
        cudaEventRecord(g_evFork, 0);
        cudaStreamWaitEvent(g_s2, g_evFork, 0);
        gemm_tf32_kernel<<<ggrid, 256, 0, g_s2>>>(x, W1, N_NODES, FIN);
        cudaEventRecord(g_evJoin, g_s2);
    } else {
        // Fallback: serial on stream 0 (verified R13 behavior).
        gemm_tf32_kernel<<<ggrid, 256>>>(x, W1, N_NODES, FIN);
    }

    // CSR build on the main (captured) stream, concurrent with gemm1.
    zero_cnt_kernel<<<NB_N, 256>>>();
    count_kernel<<<NB_E4, 256>>>(ei);
    scan_blocks_kernel<<<NB_N, 256>>>();
    scan_bsums_kernel<<<1, 256>>>(NB_N);
    scan_add_kernel<<<NB_N, 256>>>();
    fill_kernel<<<NB_E4, 256>>>(ei);

    // Join: agg1 needs both CSR and gemm1 output.
    if (g_streamOk) {
        cudaStreamWaitEvent(0, g_evJoin, 0);
    }

    agg_kernel<false><<<(N_NODES * 32 + 255) / 256, 256>>>(b1, nullptr, nullptr, nullptr);
    gemm_f16_kernel<<<ggrid, 256>>>(W2);
    agg_kernel<true><<<(N_NODES * 32 + 255) / 256, 256>>>(b2, out, Wfc, bfc);
}